// round 4
// baseline (speedup 1.0000x reference)
#include <cuda_runtime.h>

// HyperTransposeConv: fused octonion ConvTranspose2d.
// x: [8, 512, 64, 64] f32; W: [8, 64, 32, 4, 4] f32; b: [8, 32] f32
// out: [8, 256, 128, 128] f32
//
// Decomposed by output parity into 4 dense 2x2-tap convs = implicit GEMM
// M=64 (one output row per parity), N=128 (cout tile), K=4taps*512cin.

#define CIN   512
#define COUT  256
#define HIN   64
#define HOUT  128
#define CI_SUB 64
#define CO_SUB 32

// Fused big weight, laid out [tap(ky*4+kx): 16][cin: 512][cout: 256]
__device__ float WBIG[16 * CIN * COUT];
__device__ float BBIG[COUT];

struct CompT { int v[8][8]; };

__global__ void prep_w_kernel(const float* __restrict__ W, CompT comp) {
    int t = blockIdx.x * blockDim.x + threadIdx.x;
    if (t >= 16 * CIN * COUT) return;
    int co  = t & (COUT - 1);
    int ci  = (t >> 8) & (CIN - 1);
    int tap = t >> 17;              // ky*4+kx
    int ky = tap >> 2, kx = tap & 3;
    int j = ci >> 6, a = ci & 63;   // input component, sub-channel
    int i = co >> 5, c = co & 31;   // output component, sub-channel
    int v = comp.v[i][j];
    float s = (v < 0) ? -1.0f : 1.0f;
    int id = (v < 0) ? -v : v;
    // W layout: [comp(8)][c_in 64][c_out 32][ky 4][kx 4]
    WBIG[t] = s * W[((id * CI_SUB + a) * CO_SUB + c) * 16 + ky * 4 + kx];
}

__global__ void prep_b_kernel(const float* __restrict__ bsrc, CompT comp) {
    int co = threadIdx.x;            // 256 threads
    int i = co >> 5, c = co & 31;
    float s = 0.0f;
    #pragma unroll
    for (int j = 0; j < 8; ++j) {
        int v = comp.v[i][j];
        float sg = (v < 0) ? -1.0f : 1.0f;
        int id = (v < 0) ? -v : v;
        s += sg * bsrc[id * CO_SUB + c];
    }
    BBIG[co] = s;
}

__global__ __launch_bounds__(256) void hconv_kernel(
    const float* __restrict__ x, float* __restrict__ out)
{
    // smem: As[16][64] (4KB) + Bs[16][128] (8KB); epilogue reuses as 32x68 buffer
    __shared__ float sm[16 * 64 + 16 * 128];
    float* As = sm;
    float* Bs = sm + 16 * 64;

    const int tid = threadIdx.x;
    const int tx = tid & 15, ty = tid >> 4;
    const int ty4 = ty * 4, tx8 = tx * 8;

    const int co0 = blockIdx.x * 128;     // cout tile base (0 or 128)
    const int y   = blockIdx.y;           // 0..63 output row (per parity)
    const int z   = blockIdx.z;           // b*4 + parity
    const int b   = z >> 2;
    const int py  = (z >> 1) & 1;
    const int px  = z & 1;

    // transpose-conv taps per parity:  i = (o + pad - k) / stride
    int kyA[2], iyA[2], kxA[2], dxA[2];
    if (py == 0) { kyA[0] = 1; iyA[0] = y;     kyA[1] = 3; iyA[1] = y - 1; }
    else         { kyA[0] = 0; iyA[0] = y + 1; kyA[1] = 2; iyA[1] = y;     }
    if (px == 0) { kxA[0] = 1; dxA[0] = 0;     kxA[1] = 3; dxA[1] = -1;    }
    else         { kxA[0] = 0; dxA[0] = 1;     kxA[1] = 2; dxA[1] = 0;     }

    float acc[4][8];
    #pragma unroll
    for (int i = 0; i < 4; ++i)
        #pragma unroll
        for (int jj = 0; jj < 8; ++jj) acc[i][jj] = 0.0f;

    const int xcol = tid & 63;   // A loader: pixel column
    const int crow = tid >> 6;   // A loader: cin row group (0..3)
    const int bcol = tid & 31;   // B loader: co float4 column
    const int brow = tid >> 5;   // B loader: cin row (0..7)

    for (int tt = 0; tt < 4; ++tt) {
        const int tyi = tt >> 1, txi = tt & 1;
        const int iy = iyA[tyi];
        if ((unsigned)iy >= (unsigned)HIN) continue;   // block-uniform skip
        const int dx = dxA[txi];
        const float* wb = WBIG + ((kyA[tyi] * 4 + kxA[txi]) << 17) + co0;
        const float* xp = x + ((long long)(b * CIN) * HIN + iy) * HIN;
        const int ix = xcol + dx;
        const bool okx = (unsigned)ix < (unsigned)HIN;

        for (int c0 = 0; c0 < CIN; c0 += 16) {
            // load A chunk: 16 cin x 64 pixels (coalesced along x)
            #pragma unroll
            for (int r = 0; r < 4; ++r) {
                const int cl = crow + r * 4;
                float v = 0.0f;
                if (okx) v = xp[(c0 + cl) * (HIN * HIN) + ix];
                As[cl * 64 + xcol] = v;
            }
            // load B chunk: 16 cin x 128 cout (float4, coalesced)
            #pragma unroll
            for (int r = 0; r < 2; ++r) {
                const int rr = brow + r * 8;
                *(float4*)&Bs[rr * 128 + bcol * 4] =
                    *(const float4*)&wb[(c0 + rr) * COUT + bcol * 4];
            }
            __syncthreads();
            #pragma unroll
            for (int k = 0; k < 16; ++k) {
                const float4 a4 = *(const float4*)&As[k * 64 + ty4];
                const float4 b0 = *(const float4*)&Bs[k * 128 + tx8];
                const float4 b1 = *(const float4*)&Bs[k * 128 + tx8 + 4];
                const float av[4] = {a4.x, a4.y, a4.z, a4.w};
                const float bv[8] = {b0.x, b0.y, b0.z, b0.w,
                                     b1.x, b1.y, b1.z, b1.w};
                #pragma unroll
                for (int i = 0; i < 4; ++i)
                    #pragma unroll
                    for (int jj = 0; jj < 8; ++jj)
                        acc[i][jj] += av[i] * bv[jj];
            }
            __syncthreads();
        }
    }

    // Epilogue: transpose through smem so global stores are x-contiguous
    // (stride-2 in ox -> only 2x sector amplification instead of 8x).
    const int oy = 2 * y + py;
    float* outp = out + ((long long)b * COUT) * (HOUT * HOUT);
    const int r0 = tid >> 6;
    const int ox = 2 * xcol + px;
    for (int cb = 0; cb < 4; ++cb) {
        __syncthreads();
        if ((tx >> 2) == cb) {
            #pragma unroll
            for (int jj = 0; jj < 8; ++jj) {
                const int n = (tx & 3) * 8 + jj;   // local co within 32-group
                #pragma unroll
                for (int i = 0; i < 4; ++i)
                    sm[n * 68 + ty4 + i] = acc[i][jj];
            }
        }
        __syncthreads();
        #pragma unroll
        for (int rr = 0; rr < 8; ++rr) {
            const int row = r0 + rr * 4;          // 0..31
            const int co = co0 + cb * 32 + row;
            outp[(co * HOUT + oy) * HOUT + ox] = sm[row * 68 + xcol] + BBIG[co];
        }
    }
}

extern "C" void kernel_launch(void* const* d_in, const int* in_sizes, int n_in,
                              void* d_out, int out_size)
{
    const float* x  = (const float*)d_in[0];
    const float* W  = (const float*)d_in[1];
    const float* bb = (const float*)d_in[2];
    float* out = (float*)d_out;

    // Cayley-Dickson component table (host-side, passed by value: no memcpy)
    CompT comp;
    comp.v[0][0] = 0;
    for (int m = 1; m < 8; m <<= 1)
        for (int i = 0; i < m; ++i)
            for (int j = 0; j < m; ++j) {
                const int a = comp.v[i][j];
                comp.v[i][j + m] = -(a + m);
                comp.v[i + m][j] = a + m;
                comp.v[i + m][j + m] = a;
            }

    prep_w_kernel<<<(16 * CIN * COUT + 255) / 256, 256>>>(W, comp);
    prep_b_kernel<<<1, 256>>>(bb, comp);

    dim3 grid(2, 64, 32);   // (cout tiles, output rows, batch*parity)
    hconv_kernel<<<grid, 256>>>(x, out);
}